// round 5
// baseline (speedup 1.0000x reference)
#include <cuda_runtime.h>
#include <math.h>

#define N_ROWS 32768
#define DIM    512
#define NQ     8
#define NK     4096

// Scratch (allocation-free rule: __device__ globals).
// Referenced by name inside kernels only — never passed from host.
__device__ float g_res[(size_t)N_ROWS * DIM];    // 64 MB running residual
__device__ float g_anorm[(size_t)N_ROWS * DIM];  // 64 MB normalized residual
__device__ float g_bnorm[(size_t)NK * DIM];      //  8 MB normalized codebook (stage)
__device__ float g_rnorm[N_ROWS];                // per-row residual norms
__device__ float g_cnorm[NK];                    // per-codeword norms
__device__ int   g_ids[N_ROWS];                  // per-stage argmax ids

// ---------------------------------------------------------------------------
// init: res = x, hard(out) = 0
// ---------------------------------------------------------------------------
__global__ __launch_bounds__(256) void init_kernel(const float* __restrict__ x,
                                                   float* __restrict__ hard) {
    size_t i = ((size_t)blockIdx.x * 256 + threadIdx.x) * 4;
    float4 v = *(const float4*)(x + i);
    *(float4*)(g_res + i) = v;
    *(float4*)(hard + i) = make_float4(0.f, 0.f, 0.f, 0.f);
}

// ---------------------------------------------------------------------------
// Row L2 norm, STRICT SEQUENTIAL fp32 (k ascending, mul then add, no fma,
// no reassociation) — replicating XLA:CPU's scalar reduce emitter bits.
// n = max(sqrtf(sum), 1e-12). One thread per row.
// ---------------------------------------------------------------------------
__device__ __forceinline__ float seq_row_norm(const float* __restrict__ s) {
    float acc = 0.f;
    #pragma unroll 8
    for (int i = 0; i < DIM; i += 4) {
        float4 v = *(const float4*)(s + i);
        acc = __fadd_rn(acc, __fmul_rn(v.x, v.x));
        acc = __fadd_rn(acc, __fmul_rn(v.y, v.y));
        acc = __fadd_rn(acc, __fmul_rn(v.z, v.z));
        acc = __fadd_rn(acc, __fmul_rn(v.w, v.w));
    }
    return fmaxf(__fsqrt_rn(acc), 1e-12f);
}

__global__ __launch_bounds__(256) void res_norm_kernel() {
    int r = blockIdx.x * 256 + threadIdx.x;          // 0..N_ROWS-1
    g_rnorm[r] = seq_row_norm(g_res + (size_t)r * DIM);
}

__global__ __launch_bounds__(256) void cb_norm_kernel(const float* __restrict__ cbq) {
    int r = blockIdx.x * 256 + threadIdx.x;          // 0..NK-1
    g_cnorm[r] = seq_row_norm(cbq + (size_t)r * DIM);
}

// order-free elementwise divide (IEEE rn), coalesced
__global__ __launch_bounds__(256) void res_div_kernel() {
    size_t i = ((size_t)blockIdx.x * 256 + threadIdx.x) * 4;
    float n = g_rnorm[i >> 9];                       // i / DIM
    float4 v = *(const float4*)(g_res + i);
    float4 o;
    o.x = __fdiv_rn(v.x, n); o.y = __fdiv_rn(v.y, n);
    o.z = __fdiv_rn(v.z, n); o.w = __fdiv_rn(v.w, n);
    *(float4*)(g_anorm + i) = o;
}

__global__ __launch_bounds__(256) void cb_div_kernel(const float* __restrict__ cbq) {
    size_t i = ((size_t)blockIdx.x * 256 + threadIdx.x) * 4;
    float n = g_cnorm[i >> 9];
    float4 v = *(const float4*)(cbq + i);
    float4 o;
    o.x = __fdiv_rn(v.x, n); o.y = __fdiv_rn(v.y, n);
    o.z = __fdiv_rn(v.z, n); o.w = __fdiv_rn(v.w, n);
    *(float4*)(g_bnorm + i) = o;
}

// ---------------------------------------------------------------------------
// Fused GEMM (anorm @ bnorm^T) + row argmax.  (UNCHANGED from round 4.)
// Tile 128x128x32, 256 threads, 8x8 micro-tile, strided fragment ownership.
// Each output element is ONE fmaf chain over k = 0..511 ascending ->
// bit-identical to a sequential-FMA (Eigen gebp) reference accumulation.
// ---------------------------------------------------------------------------
__global__ __launch_bounds__(256) void gemm_argmax_kernel() {
    __shared__ float As[32][130];
    __shared__ float Bs[32][130];

    const int tid  = threadIdx.x;
    const int tx   = tid & 15;       // column group
    const int ty   = tid >> 4;       // row group
    const int row0 = blockIdx.x * 128;

    float best[8];
    int   bidx[8];
    #pragma unroll
    for (int i = 0; i < 8; i++) { best[i] = -3.4e38f; bidx[i] = 0; }

    for (int ct = 0; ct < NK; ct += 128) {
        float acc[8][8];
        #pragma unroll
        for (int i = 0; i < 8; i++)
            #pragma unroll
            for (int j = 0; j < 8; j++) acc[i][j] = 0.f;

        for (int kk = 0; kk < DIM; kk += 32) {
            __syncthreads();
            #pragma unroll
            for (int t = 0; t < 4; t++) {
                int f = tid + t * 256;           // 0..1023 float4 slots
                int r = f >> 3;                  // 0..127 tile row
                int c = (f & 7) << 2;            // 0,4,...,28 within k-slab
                float4 va = *(const float4*)(g_anorm + (size_t)(row0 + r) * DIM + kk + c);
                As[c + 0][r] = va.x; As[c + 1][r] = va.y;
                As[c + 2][r] = va.z; As[c + 3][r] = va.w;
                float4 vb = *(const float4*)(g_bnorm + (size_t)(ct + r) * DIM + kk + c);
                Bs[c + 0][r] = vb.x; Bs[c + 1][r] = vb.y;
                Bs[c + 2][r] = vb.z; Bs[c + 3][r] = vb.w;
            }
            __syncthreads();

            #pragma unroll
            for (int k = 0; k < 32; k++) {
                float a[8], b[8];
                #pragma unroll
                for (int i = 0; i < 8; i++) a[i] = As[k][ty + 16 * i];
                #pragma unroll
                for (int j = 0; j < 8; j++) b[j] = Bs[k][tx + 16 * j];
                #pragma unroll
                for (int i = 0; i < 8; i++)
                    #pragma unroll
                    for (int j = 0; j < 8; j++)
                        acc[i][j] = __fmaf_rn(a[i], b[j], acc[i][j]);
            }
        }

        // argmax update: columns visited ascending per thread -> strict '>'
        // gives first-index tie-break, matching jnp.argmax.
        #pragma unroll
        for (int j = 0; j < 8; j++) {
            int col = ct + tx + 16 * j;
            #pragma unroll
            for (int i = 0; i < 8; i++) {
                float v = acc[i][j];
                if (v > best[i]) { best[i] = v; bidx[i] = col; }
            }
        }
    }

    // reduce across the 16 tx-lanes sharing each row (lowest index wins ties)
    #pragma unroll
    for (int off = 8; off; off >>= 1) {
        #pragma unroll
        for (int i = 0; i < 8; i++) {
            float ov = __shfl_xor_sync(0xffffffffu, best[i], off);
            int   oi = __shfl_xor_sync(0xffffffffu, bidx[i], off);
            if (ov > best[i] || (ov == best[i] && oi < bidx[i])) {
                best[i] = ov; bidx[i] = oi;
            }
        }
    }
    if (tx == 0) {
        #pragma unroll
        for (int i = 0; i < 8; i++) g_ids[row0 + ty + 16 * i] = bidx[i];
    }
}

// ---------------------------------------------------------------------------
// residual update: res -= cb[id], hard += cb[id], emit id (cast to float)
// ---------------------------------------------------------------------------
__global__ __launch_bounds__(256) void update_kernel(const float* __restrict__ cb,
                                                     float* __restrict__ hard,
                                                     float* __restrict__ out_ids,
                                                     int q) {
    int t   = blockIdx.x * 256 + threadIdx.x;
    int row = t >> 7;
    int c   = (t & 127) << 2;
    int id  = g_ids[row];
    float4 cv = *(const float4*)(cb + (size_t)id * DIM + c);
    size_t off = (size_t)row * DIM + c;
    float4 r = *(float4*)(g_res + off);
    r.x -= cv.x; r.y -= cv.y; r.z -= cv.z; r.w -= cv.w;
    *(float4*)(g_res + off) = r;
    float4 h = *(float4*)(hard + off);
    h.x += cv.x; h.y += cv.y; h.z += cv.z; h.w += cv.w;
    *(float4*)(hard + off) = h;
    if (out_ids != nullptr && (t & 127) == 0)
        out_ids[(size_t)row * NQ + q] = (float)id;
}

// ---------------------------------------------------------------------------
extern "C" void kernel_launch(void* const* d_in, const int* in_sizes, int n_in,
                              void* d_out, int out_size) {
    const float* x  = (const float*)d_in[0];   // [N, D] fp32
    const float* cb = (const float*)d_in[1];   // [Q, K, D] fp32
    float* out      = (float*)d_out;

    const size_t nd = (size_t)N_ROWS * DIM;
    float* out_ids  = ((size_t)out_size >= nd + (size_t)N_ROWS * NQ)
                      ? out + nd : nullptr;

    init_kernel<<<N_ROWS * DIM / 1024, 256>>>(x, out);

    for (int q = 0; q < NQ; q++) {
        const float* cbq = cb + (size_t)q * NK * DIM;
        cb_norm_kernel<<<NK / 256, 256>>>(cbq);
        cb_div_kernel<<<NK * DIM / 1024, 256>>>(cbq);
        res_norm_kernel<<<N_ROWS / 256, 256>>>();
        res_div_kernel<<<N_ROWS * DIM / 1024, 256>>>();
        gemm_argmax_kernel<<<N_ROWS / 128, 256>>>();
        update_kernel<<<N_ROWS * 128 / 256, 256>>>(cbq, out, out_ids, q);
    }
}

// round 6
// speedup vs baseline: 1.1704x; 1.1704x over previous
#include <cuda_runtime.h>
#include <math.h>

#define N_ROWS 32768
#define DIM    512
#define NQ     8
#define NK     4096

// Scratch (allocation-free rule: __device__ globals).
// Referenced by name inside kernels only — never passed from host.
__device__ float g_res[(size_t)N_ROWS * DIM];    // 64 MB running residual
__device__ float g_anorm[(size_t)N_ROWS * DIM];  // 64 MB normalized residual
__device__ float g_bnorm[(size_t)NK * DIM];      //  8 MB normalized codebook (stage)
__device__ float g_rnorm[N_ROWS];                // per-row residual norms
__device__ float g_cnorm[NK];                    // per-codeword norms
__device__ int   g_ids[N_ROWS];                  // per-stage argmax ids

// ---------------------------------------------------------------------------
// packed f32x2 helpers: each lane is an independent IEEE-754 rn op, so the
// per-element fmaf chains remain bit-identical to scalar __fmaf_rn chains.
// ---------------------------------------------------------------------------
__device__ __forceinline__ unsigned long long packf2(float lo, float hi) {
    unsigned long long r;
    asm("mov.b64 %0, {%1, %2};" : "=l"(r) : "f"(lo), "f"(hi));
    return r;
}
__device__ __forceinline__ void fmaf2(unsigned long long& d,
                                      unsigned long long a,
                                      unsigned long long b) {
    asm("fma.rn.f32x2 %0, %1, %2, %0;" : "+l"(d) : "l"(a), "l"(b));
}
__device__ __forceinline__ void unpackf2(unsigned long long p, float& lo, float& hi) {
    asm("mov.b64 {%0, %1}, %2;" : "=f"(lo), "=f"(hi) : "l"(p));
}

// ---------------------------------------------------------------------------
// init: res = x, hard(out) = 0
// ---------------------------------------------------------------------------
__global__ __launch_bounds__(256) void init_kernel(const float* __restrict__ x,
                                                   float* __restrict__ hard) {
    size_t i = ((size_t)blockIdx.x * 256 + threadIdx.x) * 4;
    float4 v = *(const float4*)(x + i);
    *(float4*)(g_res + i) = v;
    *(float4*)(hard + i) = make_float4(0.f, 0.f, 0.f, 0.f);
}

// ---------------------------------------------------------------------------
// Row L2 norm, STRICT SEQUENTIAL fp32 (k ascending, mul then add, no fma,
// no reassociation) — replicating XLA:CPU's scalar reduce emitter bits.
// n = max(sqrtf(sum), 1e-12). One thread per row.
// ---------------------------------------------------------------------------
__device__ __forceinline__ float seq_row_norm(const float* __restrict__ s) {
    float acc = 0.f;
    #pragma unroll 8
    for (int i = 0; i < DIM; i += 4) {
        float4 v = *(const float4*)(s + i);
        acc = __fadd_rn(acc, __fmul_rn(v.x, v.x));
        acc = __fadd_rn(acc, __fmul_rn(v.y, v.y));
        acc = __fadd_rn(acc, __fmul_rn(v.z, v.z));
        acc = __fadd_rn(acc, __fmul_rn(v.w, v.w));
    }
    return fmaxf(__fsqrt_rn(acc), 1e-12f);
}

__global__ __launch_bounds__(256) void res_norm_kernel() {
    int r = blockIdx.x * 256 + threadIdx.x;          // 0..N_ROWS-1
    g_rnorm[r] = seq_row_norm(g_res + (size_t)r * DIM);
}

__global__ __launch_bounds__(256) void cb_norm_kernel(const float* __restrict__ cbq) {
    int r = blockIdx.x * 256 + threadIdx.x;          // 0..NK-1
    g_cnorm[r] = seq_row_norm(cbq + (size_t)r * DIM);
}

// order-free elementwise divide (IEEE rn), coalesced
__global__ __launch_bounds__(256) void res_div_kernel() {
    size_t i = ((size_t)blockIdx.x * 256 + threadIdx.x) * 4;
    float n = g_rnorm[i >> 9];                       // i / DIM
    float4 v = *(const float4*)(g_res + i);
    float4 o;
    o.x = __fdiv_rn(v.x, n); o.y = __fdiv_rn(v.y, n);
    o.z = __fdiv_rn(v.z, n); o.w = __fdiv_rn(v.w, n);
    *(float4*)(g_anorm + i) = o;
}

__global__ __launch_bounds__(256) void cb_div_kernel(const float* __restrict__ cbq) {
    size_t i = ((size_t)blockIdx.x * 256 + threadIdx.x) * 4;
    float n = g_cnorm[i >> 9];
    float4 v = *(const float4*)(cbq + i);
    float4 o;
    o.x = __fdiv_rn(v.x, n); o.y = __fdiv_rn(v.y, n);
    o.z = __fdiv_rn(v.z, n); o.w = __fdiv_rn(v.w, n);
    *(float4*)(g_bnorm + i) = o;
}

// ---------------------------------------------------------------------------
// Fused GEMM (anorm @ bnorm^T) + row argmax, packed-f32x2 math pipe.
// Tile 128x128x32, 256 threads. Thread (tx,ty) owns row pairs {2ty+32i,+1}
// (i=0..3) and col pairs {2tx+32j,+1} (j=0..3): 8x8 outputs as 32 f32x2
// accumulators. Each output element remains ONE fmaf chain over k ascending
// -> bit-identical to the sequential reference accumulation.
// ---------------------------------------------------------------------------
__global__ __launch_bounds__(256) void gemm_argmax_kernel() {
    __shared__ float As[32][130];
    __shared__ float Bs[32][130];

    const int tid  = threadIdx.x;
    const int tx   = tid & 15;       // column-pair group
    const int ty   = tid >> 4;       // row-pair group
    const int row0 = blockIdx.x * 128;

    float best[8];
    int   bidx[8];
    #pragma unroll
    for (int r = 0; r < 8; r++) { best[r] = -3.4e38f; bidx[r] = 0; }

    for (int ct = 0; ct < NK; ct += 128) {
        unsigned long long accp[8][4];
        #pragma unroll
        for (int r = 0; r < 8; r++)
            #pragma unroll
            for (int j = 0; j < 4; j++) accp[r][j] = 0ull;

        for (int kk = 0; kk < DIM; kk += 32) {
            __syncthreads();
            #pragma unroll
            for (int t = 0; t < 4; t++) {
                int f = tid + t * 256;           // 0..1023 float4 slots
                int r = f >> 3;                  // 0..127 tile row
                int c = (f & 7) << 2;            // 0,4,...,28 within k-slab
                float4 va = *(const float4*)(g_anorm + (size_t)(row0 + r) * DIM + kk + c);
                As[c + 0][r] = va.x; As[c + 1][r] = va.y;
                As[c + 2][r] = va.z; As[c + 3][r] = va.w;
                float4 vb = *(const float4*)(g_bnorm + (size_t)(ct + r) * DIM + kk + c);
                Bs[c + 0][r] = vb.x; Bs[c + 1][r] = vb.y;
                Bs[c + 2][r] = vb.z; Bs[c + 3][r] = vb.w;
            }
            __syncthreads();

            #pragma unroll
            for (int k = 0; k < 32; k++) {
                unsigned long long bp[4];
                #pragma unroll
                for (int j = 0; j < 4; j++) {
                    float2 b2 = *(const float2*)&Bs[k][2 * tx + 32 * j];
                    bp[j] = packf2(b2.x, b2.y);
                }
                #pragma unroll
                for (int i = 0; i < 4; i++) {
                    float2 a2 = *(const float2*)&As[k][2 * ty + 32 * i];
                    unsigned long long ap0 = packf2(a2.x, a2.x);
                    unsigned long long ap1 = packf2(a2.y, a2.y);
                    #pragma unroll
                    for (int j = 0; j < 4; j++) {
                        fmaf2(accp[2 * i + 0][j], ap0, bp[j]);
                        fmaf2(accp[2 * i + 1][j], ap1, bp[j]);
                    }
                }
            }
        }

        // argmax update: per thread, columns visited strictly ascending
        // (j asc, lo before hi) -> strict '>' keeps first index (jnp.argmax).
        #pragma unroll
        for (int j = 0; j < 4; j++) {
            int c0 = ct + 2 * tx + 32 * j;
            #pragma unroll
            for (int r = 0; r < 8; r++) {
                float v0, v1;
                unpackf2(accp[r][j], v0, v1);
                if (v0 > best[r]) { best[r] = v0; bidx[r] = c0; }
                if (v1 > best[r]) { best[r] = v1; bidx[r] = c0 + 1; }
            }
        }
    }

    // reduce across the 16 tx-lanes sharing each row (lowest index wins ties)
    #pragma unroll
    for (int off = 8; off; off >>= 1) {
        #pragma unroll
        for (int r = 0; r < 8; r++) {
            float ov = __shfl_xor_sync(0xffffffffu, best[r], off);
            int   oi = __shfl_xor_sync(0xffffffffu, bidx[r], off);
            if (ov > best[r] || (ov == best[r] && oi < bidx[r])) {
                best[r] = ov; bidx[r] = oi;
            }
        }
    }
    if (tx == 0) {
        #pragma unroll
        for (int r = 0; r < 8; r++) {
            int row = row0 + 2 * ty + 32 * (r >> 1) + (r & 1);
            g_ids[row] = bidx[r];
        }
    }
}

// ---------------------------------------------------------------------------
// residual update: res -= cb[id], hard += cb[id], emit id (cast to float)
// ---------------------------------------------------------------------------
__global__ __launch_bounds__(256) void update_kernel(const float* __restrict__ cb,
                                                     float* __restrict__ hard,
                                                     float* __restrict__ out_ids,
                                                     int q) {
    int t   = blockIdx.x * 256 + threadIdx.x;
    int row = t >> 7;
    int c   = (t & 127) << 2;
    int id  = g_ids[row];
    float4 cv = *(const float4*)(cb + (size_t)id * DIM + c);
    size_t off = (size_t)row * DIM + c;
    float4 r = *(float4*)(g_res + off);
    r.x -= cv.x; r.y -= cv.y; r.z -= cv.z; r.w -= cv.w;
    *(float4*)(g_res + off) = r;
    float4 h = *(float4*)(hard + off);
    h.x += cv.x; h.y += cv.y; h.z += cv.z; h.w += cv.w;
    *(float4*)(hard + off) = h;
    if (out_ids != nullptr && (t & 127) == 0)
        out_ids[(size_t)row * NQ + q] = (float)id;
}

// ---------------------------------------------------------------------------
extern "C" void kernel_launch(void* const* d_in, const int* in_sizes, int n_in,
                              void* d_out, int out_size) {
    const float* x  = (const float*)d_in[0];   // [N, D] fp32
    const float* cb = (const float*)d_in[1];   // [Q, K, D] fp32
    float* out      = (float*)d_out;

    const size_t nd = (size_t)N_ROWS * DIM;
    float* out_ids  = ((size_t)out_size >= nd + (size_t)N_ROWS * NQ)
                      ? out + nd : nullptr;

    init_kernel<<<N_ROWS * DIM / 1024, 256>>>(x, out);

    for (int q = 0; q < NQ; q++) {
        const float* cbq = cb + (size_t)q * NK * DIM;
        cb_norm_kernel<<<NK / 256, 256>>>(cbq);
        cb_div_kernel<<<NK * DIM / 1024, 256>>>(cbq);
        res_norm_kernel<<<N_ROWS / 256, 256>>>();
        res_div_kernel<<<N_ROWS * DIM / 1024, 256>>>();
        gemm_argmax_kernel<<<N_ROWS / 128, 256>>>();
        update_kernel<<<N_ROWS * 128 / 256, 256>>>(cbq, out, out_ids, q);
    }
}